// round 7
// baseline (speedup 1.0000x reference)
#include <cuda_runtime.h>
#include <cuda_bf16.h>
#include <math.h>
#include <stdint.h>

#define NB 16
#define T1V 800
#define T2V 200

extern __shared__ char smem_dyn[];

// Intermediates (no allocation allowed -> __device__ globals)
__device__ float g_kh [NB*512*200];   // key conv1 out (post-relu)
__device__ float g_k  [NB*80*200];    // key encoder out
__device__ float g_qh1[NB*160*800];   // query conv1 out (post-relu)
__device__ float g_qh2[NB*80*800];    // query conv2 out (post-relu)
__device__ float g_q  [NB*80*800];    // query encoder out

// Pre-transposed, zero-padded bf16 weights: Wt[kap][m], kap = kk*CIN + cin
__device__ __nv_bfloat16 g_wt1 [768*512];
__device__ __nv_bfloat16 g_wt2 [512*80];
__device__ __nv_bfloat16 g_wtq1[256*160];
__device__ __nv_bfloat16 g_wtq2[160*80];
__device__ __nv_bfloat16 g_wtq3[ 96*80];

// ---------------- mma/ldmatrix helpers (baseline PTX, sm_103-safe) ----------------
__device__ __forceinline__ uint32_t smem_u32(const void* p) {
    uint32_t a;
    asm("{ .reg .u64 t; cvta.to.shared.u64 t, %1; cvt.u32.u64 %0, t; }" : "=r"(a) : "l"(p));
    return a;
}
__device__ __forceinline__ void ldsm4t(uint32_t r[4], uint32_t addr) {
    asm volatile("ldmatrix.sync.aligned.m8n8.x4.trans.shared.b16 {%0,%1,%2,%3}, [%4];"
                 : "=r"(r[0]), "=r"(r[1]), "=r"(r[2]), "=r"(r[3]) : "r"(addr));
}
__device__ __forceinline__ void mma16816(float c[4], const uint32_t a[4],
                                         uint32_t b0, uint32_t b1) {
    asm volatile("mma.sync.aligned.m16n8k16.row.col.f32.bf16.bf16.f32 "
                 "{%0,%1,%2,%3}, {%4,%5,%6,%7}, {%8,%9}, {%0,%1,%2,%3};"
                 : "+f"(c[0]), "+f"(c[1]), "+f"(c[2]), "+f"(c[3])
                 : "r"(a[0]), "r"(a[1]), "r"(a[2]), "r"(a[3]), "r"(b0), "r"(b1));
}

// ---------------- weight prep: W[m][cin][kk] (fp32) -> Wt[kap][m] (bf16, K zero-padded) ----------------
__device__ __forceinline__ void wt_fill(__nv_bfloat16* dst, const float* W,
                                        int idx, int COUT, int CIN, int KW, int K) {
    int kap = idx / COUT, m = idx - kap * COUT;
    float v = 0.f;
    if (kap < K) {
        int kk = kap / CIN, cin = kap - kk * CIN;
        v = W[m * K + cin * KW + kk];
    }
    dst[idx] = __float2bfloat16(v);
}

__global__ __launch_bounds__(256)
void prep_weights(const float* kw1, const float* kw2, const float* qw1,
                  const float* qw2, const float* qw3) {
    const int s1 = 768*512, s2 = 512*80, s3 = 256*160, s4 = 160*80, s5 = 96*80;
    int idx = blockIdx.x * 256 + threadIdx.x;
    if (idx < s1) { wt_fill(g_wt1, kw1, idx, 512, 256, 3, 768); return; }
    idx -= s1;
    if (idx < s2) { wt_fill(g_wt2, kw2, idx, 80, 512, 1, 512); return; }
    idx -= s2;
    if (idx < s3) { wt_fill(g_wtq1, qw1, idx, 160, 80, 3, 240); return; }
    idx -= s3;
    if (idx < s4) { wt_fill(g_wtq2, qw2, idx, 80, 160, 1, 160); return; }
    idx -= s4;
    if (idx < s5) { wt_fill(g_wtq3, qw3, idx, 80, 80, 1, 80); return; }
}

// ---------------- conv-as-GEMM via warp-level bf16 mma.sync, prefetch depth 2 ----------------
// D[m, n] = sum_kap Wt[kap][m] * B[n][kap],  B = im2col(X)^T, n = bb*T + t.
// 3 smem buffers + 2 register staging sets: LDG(kc+2) issued 2 chunk-times before STS.
template<int CIN, int COUT, int KW, int PAD, bool RELU, int T,
         int WY, int WX, int TM16, int TN8, int NC>
__device__ __forceinline__
void mma_conv(const __nv_bfloat16* __restrict__ Wt, const float* __restrict__ bias,
              const float* __restrict__ X, float* __restrict__ Y,
              int mtile, int ntile)
{
    constexpr int BM = WY * TM16 * 16;
    constexpr int BN = WX * TN8 * 8;     static_assert(BN == 128, "BN must be 128");
    constexpr int K   = CIN * KW;
    constexpr int BMp = BM + 8;
    constexpr int BNp = 136;
    constexpr int AWW = BM / 2;
    constexpr int LAW = 32 * AWW / 256;
    constexpr int LBW = 8;
    constexpr int ABYTES = 32 * BMp * 2;
    constexpr int BBYTES = 32 * BNp * 2;

    const int tid = threadIdx.x;
    const int wid = tid >> 5, lid = tid & 31;
    const int wy = wid / WX, wx = wid - wy * WX;
    const int wm0 = wy * TM16 * 16, wn0 = wx * TN8 * 8;

    const uint32_t uS = smem_u32(smem_dyn);
    uint32_t* A32[3]; uint32_t* B32[3]; uint32_t uA[3], uB[3];
#pragma unroll
    for (int p = 0; p < 3; p++) {
        A32[p] = reinterpret_cast<uint32_t*>(smem_dyn + p * ABYTES);
        B32[p] = reinterpret_cast<uint32_t*>(smem_dyn + 3 * ABYTES + p * BBYTES);
        uA[p]  = uS + p * ABYTES;
        uB[p]  = uS + 3 * ABYTES + p * BBYTES;
    }

    // ldmatrix per-lane offsets (bytes), trans layout [k][cols]
    const int g = lid >> 3, lr = lid & 7;
    const uint32_t a_off = ((lr + ((g & 2) ? 8 : 0)) * BMp + ((g & 1) ? 8 : 0)) * 2;
    const uint32_t b_off = ((lr + ((g & 1) ? 8 : 0)) * BNp + ((g & 2) ? 8 : 0)) * 2;

    float acc[TM16][TN8][4];
#pragma unroll
    for (int i = 0; i < TM16; i++)
#pragma unroll
        for (int j = 0; j < TN8; j++)
#pragma unroll
            for (int r = 0; r < 4; r++) acc[i][j][r] = 0.f;

    const uint32_t* Wt32 = reinterpret_cast<const uint32_t*>(Wt);
    const int awbase = mtile * BM / 2;

    uint32_t ra0[LAW], rb0[LBW], ra1[LAW], rb1[LBW];

    auto loadAB = [&](int kc, uint32_t* ra, uint32_t* rb) {
#pragma unroll
        for (int s = 0; s < LAW; s++) {
            int w = tid + s * 256;
            int mp = w % AWW, k = w / AWW;
            ra[s] = Wt32[(size_t)(kc * 32 + k) * (COUT / 2) + awbase + mp];
        }
#pragma unroll
        for (int s = 0; s < LBW; s++) {
            int w = tid + s * 256;
            int np = w & 63, k = w >> 6;
            int kap = kc * 32 + k;
            int n = ntile * 128 + 2 * np;
            int bb = n / T, t = n - bb * T;
            float v0 = 0.f, v1 = 0.f;
            if (kap < K) {
                if (KW == 1) {
                    const float* xr = X + (size_t)(bb * CIN + kap) * T + t;
                    v0 = xr[0]; v1 = xr[1];
                } else {
                    int kk = kap / CIN, cin = kap - kk * CIN;
                    int tin = t + kk - PAD;
                    const float* xr = X + (size_t)(bb * CIN + cin) * T;
                    if ((unsigned)tin < (unsigned)T)       v0 = xr[tin];
                    if ((unsigned)(tin + 1) < (unsigned)T) v1 = xr[tin + 1];
                }
            }
            __nv_bfloat162 h = __floats2bfloat162_rn(v0, v1);
            rb[s] = *reinterpret_cast<uint32_t*>(&h);
        }
    };
    auto stsAB = [&](int p, const uint32_t* ra, const uint32_t* rb) {
#pragma unroll
        for (int s = 0; s < LAW; s++) {
            int w = tid + s * 256;
            int mp = w % AWW, k = w / AWW;
            A32[p][k * (BMp / 2) + mp] = ra[s];
        }
#pragma unroll
        for (int s = 0; s < LBW; s++) {
            int w = tid + s * 256;
            int np = w & 63, k = w >> 6;
            B32[p][k * (BNp / 2) + np] = rb[s];
        }
    };
    auto compute = [&](int p) {
#pragma unroll
        for (int ks = 0; ks < 32; ks += 16) {
            uint32_t af[TM16][4];
#pragma unroll
            for (int i = 0; i < TM16; i++)
                ldsm4t(af[i], uA[p] + a_off + (ks * BMp + wm0 + 16 * i) * 2);
            uint32_t bf[TN8 / 2][4];
#pragma unroll
            for (int jj = 0; jj < TN8 / 2; jj++)
                ldsm4t(bf[jj], uB[p] + b_off + (ks * BNp + wn0 + 16 * jj) * 2);
#pragma unroll
            for (int i = 0; i < TM16; i++)
#pragma unroll
                for (int j = 0; j < TN8; j++)
                    mma16816(acc[i][j], af[i], bf[j >> 1][(j & 1) * 2], bf[j >> 1][(j & 1) * 2 + 1]);
        }
    };

    // prologue: chunk0 -> buf0; chunk1 load in flight (chunk c staged in reg set c%2)
    loadAB(0, ra0, rb0);
    stsAB(0, ra0, rb0);
    if (NC > 1) loadAB(1, ra1, rb1);
    __syncthreads();

    for (int kc = 0; kc < NC; kc++) {
        int p = kc % 3;
        if (kc + 2 < NC) {
            if ((kc & 1) == 0) loadAB(kc + 2, ra0, rb0);
            else               loadAB(kc + 2, ra1, rb1);
        }
        compute(p);
        if (kc + 1 < NC) {
            int pn = (kc + 1) % 3;
            if (((kc + 1) & 1) == 0) stsAB(pn, ra0, rb0);
            else                     stsAB(pn, ra1, rb1);
            __syncthreads();
        }
    }

    // epilogue: direct float2 stores (all tile dims divide exactly)
#pragma unroll
    for (int i = 0; i < TM16; i++) {
        int r0 = mtile * BM + wm0 + 16 * i + (lid >> 2);
        float bv0 = bias[r0], bv1 = bias[r0 + 8];
#pragma unroll
        for (int j = 0; j < TN8; j++) {
            int n = ntile * 128 + wn0 + 8 * j + (lid & 3) * 2;
            int bb = n / T, t = n - bb * T;
            float2 v0, v1;
            v0.x = acc[i][j][0] + bv0; v0.y = acc[i][j][1] + bv0;
            v1.x = acc[i][j][2] + bv1; v1.y = acc[i][j][3] + bv1;
            if (RELU) {
                v0.x = fmaxf(v0.x, 0.f); v0.y = fmaxf(v0.y, 0.f);
                v1.x = fmaxf(v1.x, 0.f); v1.y = fmaxf(v1.y, 0.f);
            }
            *reinterpret_cast<float2*>(&Y[(size_t)(bb * COUT + r0) * T + t])     = v0;
            *reinterpret_cast<float2*>(&Y[(size_t)(bb * COUT + r0 + 8) * T + t]) = v1;
        }
    }
}

// Launch A: z=0 -> key conv1 [100 CTAs], z=1 -> query conv1 [200 CTAs],
//           z=2 -> logprior (log(prior+1e-8) -> out) [200 CTAs, MUFU hides under convs]
__global__ __launch_bounds__(256)
void fusedA(const float* __restrict__ kb1, const float* __restrict__ keys, float* __restrict__ kh,
            const float* __restrict__ qb1, const float* __restrict__ queries, float* __restrict__ qh1,
            const float* __restrict__ prior, float* __restrict__ out)
{
    int bx = blockIdx.x;
    if (blockIdx.z == 0) {
        if (bx >= 100) return;
        mma_conv<256, 512, 3, 1, true, 200, 2, 4, 4, 4, 24>(g_wt1, kb1, keys, kh, bx / 25, bx % 25);
    } else if (blockIdx.z == 1) {
        mma_conv<80, 160, 3, 1, true, 800, 1, 8, 5, 2, 8>(g_wtq1, qb1, queries, qh1, bx / 100, bx % 100);
    } else {
        // logprior: 2.56M elems as 640K float4, grid-stride over 51200 threads
        const float4* pr4 = reinterpret_cast<const float4*>(prior);
        float4* o4 = reinterpret_cast<float4*>(out);
        for (int i = bx * 256 + threadIdx.x; i < 640000; i += 51200) {
            float4 p = pr4[i];
            float4 r;
            r.x = __logf(p.x + 1e-8f);
            r.y = __logf(p.y + 1e-8f);
            r.z = __logf(p.z + 1e-8f);
            r.w = __logf(p.w + 1e-8f);
            o4[i] = r;
        }
    }
}

// Launch B: z=0 -> key conv2 (512->80,k1) [25 CTAs], z=1 -> query conv2 (160->80,k1)+relu [100 CTAs]
__global__ __launch_bounds__(256)
void fusedB(const float* __restrict__ kb2, const float* __restrict__ kh, float* __restrict__ kout,
            const float* __restrict__ qb2, const float* __restrict__ qh1, float* __restrict__ qh2)
{
    int bx = blockIdx.x;
    if (blockIdx.z == 0) {
        if (bx >= 25) return;
        mma_conv<512, 80, 1, 0, false, 200, 1, 8, 5, 2, 16>(g_wt2, kb2, kh, kout, 0, bx);
    } else {
        mma_conv<160, 80, 1, 0, true, 800, 1, 8, 5, 2, 5>(g_wtq2, qb2, qh1, qh2, 0, bx);
    }
}

// Launch C: query conv3 (80->80,k1) [100 CTAs]
__global__ __launch_bounds__(256)
void convC(const float* __restrict__ qb3, const float* __restrict__ qh2, float* __restrict__ q)
{
    mma_conv<80, 80, 1, 0, false, 800, 1, 8, 5, 2, 3>(g_wtq3, qb3, qh2, q, 0, blockIdx.x);
}

// ---------------- final attention ----------------
// out already holds log(prior + 1e-8); add logits - logsumexp.
__global__ __launch_bounds__(256)
void attn_final(const float* __restrict__ q, const float* __restrict__ k,
                float* __restrict__ out)
{
    float* sm   = reinterpret_cast<float*>(smem_dyn);
    float* ksh  = sm;                 // [80][200]
    float* qsh  = sm + 16000;         // [32][81] transposed, padded
    float* k2sh = qsh + 32 * 81;      // [200]
    float* q2sh = k2sh + 200;         // [32]

    const int b   = blockIdx.y;
    const int t10 = blockIdx.x * 32;
    const int tid = threadIdx.x;

    for (int i = tid; i < 80 * 200; i += 256)
        ksh[i] = k[b * 16000 + i];
    for (int i = tid; i < 80 * 32; i += 256) {
        int c = i >> 5, tl = i & 31;
        qsh[tl * 81 + c] = q[(b * 80 + c) * 800 + t10 + tl];
    }
    __syncthreads();

    if (tid < 200) {
        float s = 0.f;
#pragma unroll
        for (int c = 0; c < 80; c++) { float v = ksh[c * 200 + tid]; s += v * v; }
        k2sh[tid] = s;
    }
    if (tid < 32) {
        float s = 0.f;
#pragma unroll
        for (int c = 0; c < 80; c++) { float v = qsh[tid * 81 + c]; s += v * v; }
        q2sh[tid] = s;
    }
    __syncthreads();

    const int r0 = (tid >> 4) * 2;
    const int cg = tid & 15;

    float acc0[13], acc1[13];
#pragma unroll
    for (int j = 0; j < 13; j++) { acc0[j] = 0.f; acc1[j] = 0.f; }

#pragma unroll 4
    for (int c = 0; c < 80; c++) {
        float q0 = qsh[r0 * 81 + c];
        float q1 = qsh[(r0 + 1) * 81 + c];
#pragma unroll
        for (int j = 0; j < 13; j++) {
            // j==12, cg>=8 reads stale in-bounds smem; result discarded below.
            float kv = ksh[c * 200 + cg + 16 * j];
            acc0[j] += q0 * kv;
            acc1[j] += q1 * kv;
        }
    }

    float q20 = q2sh[r0], q21 = q2sh[r0 + 1];
    float mx0 = -1e30f, mx1 = -1e30f;
#pragma unroll
    for (int j = 0; j < 13; j++) {
        int t2 = cg + 16 * j;
        if (t2 < 200) {
            acc0[j] = -5e-4f * (q20 + k2sh[t2] - 2.f * acc0[j]);
            acc1[j] = -5e-4f * (q21 + k2sh[t2] - 2.f * acc1[j]);
            mx0 = fmaxf(mx0, acc0[j]);
            mx1 = fmaxf(mx1, acc1[j]);
        }
    }
#pragma unroll
    for (int o = 8; o >= 1; o >>= 1) {
        mx0 = fmaxf(mx0, __shfl_xor_sync(0xFFFFFFFFu, mx0, o, 16));
        mx1 = fmaxf(mx1, __shfl_xor_sync(0xFFFFFFFFu, mx1, o, 16));
    }
    float s0 = 0.f, s1 = 0.f;
#pragma unroll
    for (int j = 0; j < 13; j++) {
        int t2 = cg + 16 * j;
        if (t2 < 200) {
            s0 += __expf(acc0[j] - mx0);
            s1 += __expf(acc1[j] - mx1);
        }
    }
#pragma unroll
    for (int o = 8; o >= 1; o >>= 1) {
        s0 += __shfl_xor_sync(0xFFFFFFFFu, s0, o, 16);
        s1 += __shfl_xor_sync(0xFFFFFFFFu, s1, o, 16);
    }
    float l0 = mx0 + __logf(s0);
    float l1 = mx1 + __logf(s1);

    int base0 = (b * T1V + t10 + r0) * T2V;
    int base1 = base0 + T2V;
#pragma unroll
    for (int j = 0; j < 13; j++) {
        int t2 = cg + 16 * j;
        if (t2 < 200) {
            out[base0 + t2] = out[base0 + t2] + acc0[j] - l0;
            out[base1 + t2] = out[base1 + t2] + acc1[j] - l1;
        }
    }
}

// ---------------- launcher ----------------
extern "C" void kernel_launch(void* const* d_in, const int* in_sizes, int n_in,
                              void* d_out, int out_size)
{
    const float* queries = (const float*)d_in[0];   // (16, 80, 800)
    const float* keys    = (const float*)d_in[1];   // (16, 256, 200)
    const float* prior   = (const float*)d_in[2];   // (16, 800, 200)
    const float* kw1 = (const float*)d_in[3];
    const float* kb1 = (const float*)d_in[4];
    const float* kw2 = (const float*)d_in[5];
    const float* kb2 = (const float*)d_in[6];
    const float* qw1 = (const float*)d_in[7];
    const float* qb1 = (const float*)d_in[8];
    const float* qw2 = (const float*)d_in[9];
    const float* qb2 = (const float*)d_in[10];
    const float* qw3 = (const float*)d_in[11];
    const float* qb3 = (const float*)d_in[12];
    float* out = (float*)d_out;

    float *p_kh, *p_k, *p_qh1, *p_qh2, *p_q;
    cudaGetSymbolAddress((void**)&p_kh,  g_kh);
    cudaGetSymbolAddress((void**)&p_k,   g_k);
    cudaGetSymbolAddress((void**)&p_qh1, g_qh1);
    cudaGetSymbolAddress((void**)&p_qh2, g_qh2);
    cudaGetSymbolAddress((void**)&p_q,   g_q);

    // 0) weight transpose/convert
    prep_weights<<<1937, 256>>>(kw1, kw2, qw1, qw2, qw3);

    // smem: 3 buffers. BM=128: 3*(32*136*2)*2 = 52224. BM=80: 3*(32*88*2 + 32*136*2) = 43008.
    const int smemA = 3 * (32 * 136 * 2) * 2;               // 52224
    const int smemB = 3 * (32 * 88 * 2 + 32 * 136 * 2);     // 43008

    cudaFuncSetAttribute(fusedA, cudaFuncAttributeMaxDynamicSharedMemorySize, smemA);
    cudaFuncSetAttribute(fusedB, cudaFuncAttributeMaxDynamicSharedMemorySize, smemB);
    cudaFuncSetAttribute(convC,  cudaFuncAttributeMaxDynamicSharedMemorySize, smemB);

    // 1) k1 (100) + q1 (200) + logprior->out (200)
    fusedA<<<dim3(200, 1, 3), 256, smemA>>>(kb1, keys, p_kh, qb1, queries, p_qh1, prior, out);
    // 2) k2 (25) + q2 (100)
    fusedB<<<dim3(100, 1, 2), 256, smemB>>>(kb2, p_kh, p_k, qb2, p_qh1, p_qh2);
    // 3) q3 (100)
    convC<<<dim3(100, 1, 1), 256, smemB>>>(qb3, p_qh2, p_q);

    // 4) distance + log-softmax, accumulate onto preloaded logprior in out
    const int smemF = (16000 + 32 * 81 + 200 + 32) * (int)sizeof(float);  // 75296 B
    cudaFuncSetAttribute(attn_final, cudaFuncAttributeMaxDynamicSharedMemorySize, smemF);
    attn_final<<<dim3(25, 16), 256, smemF>>>(p_q, p_k, out);
}